// round 10
// baseline (speedup 1.0000x reference)
#include <cuda_runtime.h>
#include <cuda_bf16.h>

// SoftIndex: per-row out[s] = cumsum_s( tanh(x[s] - x[s-1]) ), first diff = 0.
// x: [8192, 8192] fp32, out: same shape.
// R9: R4 config (592 CTAs x 256 thr, persistent dynamic row queue) + depth-3
// register prefetch streaming seamlessly across row boundaries + rotate-shfl
// neighbor (7 shfls/chunk) + self-resetting counters (single launch).

#define S 8192
#define LPT 8                 // elements per lane per chunk
#define CHUNK 256             // 32 * LPT
#define NCHUNK 32             // chunks per row
#define THREADS 256
#define GRID 592              // 4 CTAs/SM on 148 SMs
#define NWARPS (GRID * (THREADS / 32))   // 4736

__device__ unsigned int g_row_ctr = NWARPS;  // rows 0..NWARPS-1 pre-assigned
__device__ unsigned int g_done    = 0u;

// tanh(d) = 1 - 2/(ex2(d * 2/ln2) + 1); exact saturation at +/-inf.
__device__ __forceinline__ float fast_tanh(float d)
{
    float e;
    asm("ex2.approx.f32 %0, %1;" : "=f"(e) : "f"(d * 2.885390081777927f));
    float r;
    asm("rcp.approx.f32 %0, %1;" : "=f"(r) : "f"(e + 1.0f));
    return fmaf(-2.0f, r, 1.0f);
}

__device__ __forceinline__ unsigned fetch_row(unsigned lane)
{
    unsigned r;
    if (lane == 0u) r = atomicAdd(&g_row_ctr, 1u);
    return __shfl_sync(0xffffffffu, r, 0);
}

__global__ __launch_bounds__(THREADS, 4)
void softindex_kernel(const float* __restrict__ x, float* __restrict__ out)
{
    const unsigned lane  = threadIdx.x & 31u;
    const int      lbase = (int)lane * LPT;
    const int      rsrc  = (int)((lane + 31u) & 31u);  // rotate source lane

    // First row = this warp's global id (no atomic needed).
    unsigned row = blockIdx.x * (THREADS / 32) + (threadIdx.x >> 5);

    const float* __restrict__ xr   = x   + (size_t)row * S;
    float* __restrict__       orow = out + (size_t)row * S;

    // Prime depth-3 pipeline with chunks 0,1,2.
    float4 a0 = __ldcs(reinterpret_cast<const float4*>(xr + lbase));
    float4 b0 = __ldcs(reinterpret_cast<const float4*>(xr + lbase + 4));
    float4 a1 = __ldcs(reinterpret_cast<const float4*>(xr + CHUNK + lbase));
    float4 b1 = __ldcs(reinterpret_cast<const float4*>(xr + CHUNK + lbase + 4));
    float4 a2 = __ldcs(reinterpret_cast<const float4*>(xr + 2 * CHUNK + lbase));
    float4 b2 = __ldcs(reinterpret_cast<const float4*>(xr + 2 * CHUNK + lbase + 4));

    // Fetch next row id; latency hidden behind this row's 32 chunks.
    unsigned next_row = fetch_row(lane);

    for (;;) {
        const bool next_valid = next_row < (unsigned)S;
        const float* __restrict__ nxr =
            x + (size_t)(next_valid ? next_row : 0u) * S;

        float carry = 0.0f;
        float saved = 0.0f;   // lane 0: previous chunk's lane-31 last element

#pragma unroll 1
        for (int ch = 0; ch < NCHUNK; ch++) {
            // Prefetch chunk ch+3; wraps into next row's chunks 0..2.
            float4 na = make_float4(0.f, 0.f, 0.f, 0.f);
            float4 nb = na;
            const int pc = ch + 3;
            if (pc < NCHUNK) {
                const float* pn = xr + pc * CHUNK + lbase;
                na = __ldcs(reinterpret_cast<const float4*>(pn));
                nb = __ldcs(reinterpret_cast<const float4*>(pn + 4));
            } else if (next_valid) {
                const float* pn = nxr + (pc - NCHUNK) * CHUNK + lbase;
                na = __ldcs(reinterpret_cast<const float4*>(pn));
                nb = __ldcs(reinterpret_cast<const float4*>(pn + 4));
            }

            float v[LPT] = {a0.x, a0.y, a0.z, a0.w, b0.x, b0.y, b0.z, b0.w};

            // Neighbor: rotate shfl gives lane i the last element of lane i-1;
            // lane 0 receives lane 31's CURRENT value (wrong chunk) and
            // substitutes the value saved from the previous chunk's rotate.
            // At row start lane 0 uses v[0] (diff -> 0).
            const float rot = __shfl_sync(0xffffffffu, v[LPT - 1], rsrc);
            float prev = rot;
            if (lane == 0u) prev = (ch == 0) ? v[0] : saved;
            saved = rot;   // lane 0's rot == this chunk's lane-31 last element

            // Lane-local inclusive scan of tanh(diffs).
            float s[LPT];
            float run = 0.0f, p = prev;
#pragma unroll
            for (int i = 0; i < LPT; i++) {
                run += fast_tanh(v[i] - p);
                p = v[i];
                s[i] = run;
            }
            const float tot = run;

            // Warp inclusive scan of lane totals.
            float ws = tot;
#pragma unroll
            for (int off = 1; off < 32; off <<= 1) {
                float n = __shfl_up_sync(0xffffffffu, ws, off);
                if (lane >= (unsigned)off) ws += n;
            }

            const float prefix = carry + (ws - tot);   // exclusive

            float* po = orow + ch * CHUNK + lbase;
            __stcs(reinterpret_cast<float4*>(po),
                   make_float4(prefix + s[0], prefix + s[1],
                               prefix + s[2], prefix + s[3]));
            __stcs(reinterpret_cast<float4*>(po + 4),
                   make_float4(prefix + s[4], prefix + s[5],
                               prefix + s[6], prefix + s[7]));

            carry += __shfl_sync(0xffffffffu, ws, 31);

            // Rotate depth-3 pipeline.
            a0 = a1; b0 = b1;
            a1 = a2; b1 = b2;
            a2 = na; b2 = nb;
        }

        if (!next_valid) break;
        row  = next_row;
        xr   = nxr;
        orow = out + (size_t)row * S;
        next_row = fetch_row(lane);
    }

    // Last warp resets counters for the next graph replay.
    if (lane == 0u) {
        __threadfence();
        unsigned d = atomicAdd(&g_done, 1u);
        if (d == (unsigned)(NWARPS - 1)) {
            g_row_ctr = NWARPS;
            g_done    = 0u;
        }
    }
}

extern "C" void kernel_launch(void* const* d_in, const int* in_sizes, int n_in,
                              void* d_out, int out_size)
{
    const float* x = (const float*)d_in[0];
    float* out     = (float*)d_out;
    (void)in_sizes; (void)n_in; (void)out_size;

    softindex_kernel<<<GRID, THREADS>>>(x, out);
}

// round 12
// speedup vs baseline: 1.0075x; 1.0075x over previous
#include <cuda_runtime.h>
#include <cuda_bf16.h>

// SoftIndex: per-row out[s] = cumsum_s( tanh(x[s] - x[s-1]) ), first diff = 0.
// x: [8192, 8192] fp32, out: same shape.
// R9 (resubmit after infra failure): R4 config (592 CTAs x 256 thr, persistent
// dynamic row queue) + depth-3 register prefetch streaming seamlessly across
// row boundaries + rotate-shfl neighbor (7 shfls/chunk) + self-resetting
// counters (single launch).

#define S 8192
#define LPT 8                 // elements per lane per chunk
#define CHUNK 256             // 32 * LPT
#define NCHUNK 32             // chunks per row
#define THREADS 256
#define GRID 592              // 4 CTAs/SM on 148 SMs
#define NWARPS (GRID * (THREADS / 32))   // 4736

__device__ unsigned int g_row_ctr = NWARPS;  // rows 0..NWARPS-1 pre-assigned
__device__ unsigned int g_done    = 0u;

// tanh(d) = 1 - 2/(ex2(d * 2/ln2) + 1); exact saturation at +/-inf.
__device__ __forceinline__ float fast_tanh(float d)
{
    float e;
    asm("ex2.approx.f32 %0, %1;" : "=f"(e) : "f"(d * 2.885390081777927f));
    float r;
    asm("rcp.approx.f32 %0, %1;" : "=f"(r) : "f"(e + 1.0f));
    return fmaf(-2.0f, r, 1.0f);
}

__device__ __forceinline__ unsigned fetch_row(unsigned lane)
{
    unsigned r;
    if (lane == 0u) r = atomicAdd(&g_row_ctr, 1u);
    return __shfl_sync(0xffffffffu, r, 0);
}

__global__ __launch_bounds__(THREADS, 4)
void softindex_kernel(const float* __restrict__ x, float* __restrict__ out)
{
    const unsigned lane  = threadIdx.x & 31u;
    const int      lbase = (int)lane * LPT;
    const int      rsrc  = (int)((lane + 31u) & 31u);  // rotate source lane

    // First row = this warp's global id (no atomic needed).
    unsigned row = blockIdx.x * (THREADS / 32) + (threadIdx.x >> 5);

    const float* __restrict__ xr   = x   + (size_t)row * S;
    float* __restrict__       orow = out + (size_t)row * S;

    // Prime depth-3 pipeline with chunks 0,1,2.
    float4 a0 = __ldcs(reinterpret_cast<const float4*>(xr + lbase));
    float4 b0 = __ldcs(reinterpret_cast<const float4*>(xr + lbase + 4));
    float4 a1 = __ldcs(reinterpret_cast<const float4*>(xr + CHUNK + lbase));
    float4 b1 = __ldcs(reinterpret_cast<const float4*>(xr + CHUNK + lbase + 4));
    float4 a2 = __ldcs(reinterpret_cast<const float4*>(xr + 2 * CHUNK + lbase));
    float4 b2 = __ldcs(reinterpret_cast<const float4*>(xr + 2 * CHUNK + lbase + 4));

    // Fetch next row id; latency hidden behind this row's 32 chunks.
    unsigned next_row = fetch_row(lane);

    for (;;) {
        const bool next_valid = next_row < (unsigned)S;
        const float* __restrict__ nxr =
            x + (size_t)(next_valid ? next_row : 0u) * S;

        float carry = 0.0f;
        float saved = 0.0f;   // lane 0: previous chunk's lane-31 last element

#pragma unroll 1
        for (int ch = 0; ch < NCHUNK; ch++) {
            // Prefetch chunk ch+3; wraps into next row's chunks 0..2.
            float4 na = make_float4(0.f, 0.f, 0.f, 0.f);
            float4 nb = na;
            const int pc = ch + 3;
            if (pc < NCHUNK) {
                const float* pn = xr + pc * CHUNK + lbase;
                na = __ldcs(reinterpret_cast<const float4*>(pn));
                nb = __ldcs(reinterpret_cast<const float4*>(pn + 4));
            } else if (next_valid) {
                const float* pn = nxr + (pc - NCHUNK) * CHUNK + lbase;
                na = __ldcs(reinterpret_cast<const float4*>(pn));
                nb = __ldcs(reinterpret_cast<const float4*>(pn + 4));
            }

            float v[LPT] = {a0.x, a0.y, a0.z, a0.w, b0.x, b0.y, b0.z, b0.w};

            // Neighbor: rotate shfl gives lane i the last element of lane i-1;
            // lane 0 receives lane 31's CURRENT last element (wrong chunk) and
            // substitutes the value saved from the previous chunk's rotate.
            // At row start lane 0 uses v[0] (diff -> 0).
            const float rot = __shfl_sync(0xffffffffu, v[LPT - 1], rsrc);
            float prev = rot;
            if (lane == 0u) prev = (ch == 0) ? v[0] : saved;
            saved = rot;   // lane 0's rot == this chunk's lane-31 last element

            // Lane-local inclusive scan of tanh(diffs).
            float s[LPT];
            float run = 0.0f, p = prev;
#pragma unroll
            for (int i = 0; i < LPT; i++) {
                run += fast_tanh(v[i] - p);
                p = v[i];
                s[i] = run;
            }
            const float tot = run;

            // Warp inclusive scan of lane totals.
            float ws = tot;
#pragma unroll
            for (int off = 1; off < 32; off <<= 1) {
                float n = __shfl_up_sync(0xffffffffu, ws, off);
                if (lane >= (unsigned)off) ws += n;
            }

            const float prefix = carry + (ws - tot);   // exclusive

            float* po = orow + ch * CHUNK + lbase;
            __stcs(reinterpret_cast<float4*>(po),
                   make_float4(prefix + s[0], prefix + s[1],
                               prefix + s[2], prefix + s[3]));
            __stcs(reinterpret_cast<float4*>(po + 4),
                   make_float4(prefix + s[4], prefix + s[5],
                               prefix + s[6], prefix + s[7]));

            carry += __shfl_sync(0xffffffffu, ws, 31);

            // Rotate depth-3 pipeline.
            a0 = a1; b0 = b1;
            a1 = a2; b1 = b2;
            a2 = na; b2 = nb;
        }

        if (!next_valid) break;
        row  = next_row;
        xr   = nxr;
        orow = out + (size_t)row * S;
        next_row = fetch_row(lane);
    }

    // Last warp resets counters for the next graph replay.
    if (lane == 0u) {
        __threadfence();
        unsigned d = atomicAdd(&g_done, 1u);
        if (d == (unsigned)(NWARPS - 1)) {
            g_row_ctr = NWARPS;
            g_done    = 0u;
        }
    }
}

extern "C" void kernel_launch(void* const* d_in, const int* in_sizes, int n_in,
                              void* d_out, int out_size)
{
    const float* x = (const float*)d_in[0];
    float* out     = (float*)d_out;
    (void)in_sizes; (void)n_in; (void)out_size;

    softindex_kernel<<<GRID, THREADS>>>(x, out);
}

// round 13
// speedup vs baseline: 1.0524x; 1.0446x over previous
#include <cuda_runtime.h>
#include <cuda_bf16.h>

// SoftIndex: per-row out[s] = cumsum_s( tanh(x[s] - x[s-1]) ), first diff = 0.
// x: [8192, 8192] fp32, out: same shape.
// R13: quarter-row tasks (2048 elem) for 98.9% load balance. Cross-task carry
// handed off through gmem as a single 8B (epoch|float) word; task ordering
// (all q0 before q1 ...) makes the handoff poll ~always immediately ready.
// Depth-3 register prefetch streams seamlessly across task boundaries.
// Pre-kernel bumps the epoch and resets the task counter (no flag resets).

#define S 8192
#define LPT 8                  // elements per lane per chunk
#define CHUNK 256              // 32 * LPT
#define SPAN_CHUNKS 8          // chunks per task
#define SPAN 2048              // elements per task
#define QPER 4                 // tasks per row
#define NTASKS (S * QPER)      // 32768
#define THREADS 256
#define GRID 592               // 4 CTAs/SM on 148 SMs
#define NWARPS (GRID * (THREADS / 32))   // 4736

__device__ unsigned int       g_task_ctr = NWARPS;
__device__ unsigned int       g_epoch    = 0u;
__device__ unsigned long long g_hand[S * QPER];   // (epoch<<32)|float bits

__global__ void epoch_kernel()
{
    g_epoch    = g_epoch + 1u;
    g_task_ctr = NWARPS;
}

// tanh(d) = 1 - 2/(ex2(d * 2/ln2) + 1); exact saturation at +/-inf.
__device__ __forceinline__ float fast_tanh(float d)
{
    float e;
    asm("ex2.approx.f32 %0, %1;" : "=f"(e) : "f"(d * 2.885390081777927f));
    float r;
    asm("rcp.approx.f32 %0, %1;" : "=f"(r) : "f"(e + 1.0f));
    return fmaf(-2.0f, r, 1.0f);
}

__device__ __forceinline__ unsigned fetch_task(unsigned lane)
{
    unsigned r;
    if (lane == 0u) r = atomicAdd(&g_task_ctr, 1u);
    return __shfl_sync(0xffffffffu, r, 0);
}

__global__ __launch_bounds__(THREADS, 4)
void softindex_kernel(const float* __restrict__ x, float* __restrict__ out)
{
    const unsigned lane  = threadIdx.x & 31u;
    const int      lbase = (int)lane * LPT;
    const int      rsrc  = (int)((lane + 31u) & 31u);  // rotate source lane

    const unsigned epoch = *(volatile unsigned*)&g_epoch;

    // First task = warp's global id (all are q0 tasks: no dependency).
    unsigned task = blockIdx.x * (THREADS / 32) + (threadIdx.x >> 5);

    unsigned q   = task >> 13;        // 0 for the pre-assigned tasks
    unsigned row = task & (S - 1);
    const float* __restrict__ xs = x   + (size_t)row * S + (size_t)q * SPAN;
    float* __restrict__       os = out + (size_t)row * S + (size_t)q * SPAN;

    // Prime depth-3 pipeline with the first task's chunks 0,1,2.
    float4 a0 = __ldcs(reinterpret_cast<const float4*>(xs + lbase));
    float4 b0 = __ldcs(reinterpret_cast<const float4*>(xs + lbase + 4));
    float4 a1 = __ldcs(reinterpret_cast<const float4*>(xs + CHUNK + lbase));
    float4 b1 = __ldcs(reinterpret_cast<const float4*>(xs + CHUNK + lbase + 4));
    float4 a2 = __ldcs(reinterpret_cast<const float4*>(xs + 2 * CHUNK + lbase));
    float4 b2 = __ldcs(reinterpret_cast<const float4*>(xs + 2 * CHUNK + lbase + 4));

    // Next task id fetched now; latency hidden behind this task's 8 chunks.
    unsigned next_task = fetch_task(lane);

    for (;;) {
        const bool next_valid = next_task < (unsigned)NTASKS;
        const unsigned nq   = next_task >> 13;
        const unsigned nrow = next_task & (S - 1);
        const float* __restrict__ nxs =
            x + (next_valid ? ((size_t)nrow * S + (size_t)nq * SPAN) : 0u);

        // Boundary x element (x[row, q*SPAN-1]) for the first diff (q>0).
        float boundary = 0.0f;
        if (q > 0u && lane == 0u) boundary = __ldcs(xs - 1);

        // Carry entering this span: inclusive prefix of predecessor quarter.
        float carry = 0.0f;
        if (q > 0u) {
            if (lane == 0u) {
                const volatile unsigned long long* p =
                    &g_hand[(row << 2) + (q - 1u)];
                unsigned long long w;
                do { w = *p; } while ((unsigned)(w >> 32) != epoch);
                carry = __uint_as_float((unsigned)(w & 0xffffffffu));
            }
            carry = __shfl_sync(0xffffffffu, carry, 0);
        }

        float saved = 0.0f;   // lane 0: previous chunk's lane-31 last element

#pragma unroll 1
        for (int ch = 0; ch < SPAN_CHUNKS; ch++) {
            // Prefetch chunk ch+3; wraps into the next task's chunks 0..2.
            float4 na = make_float4(0.f, 0.f, 0.f, 0.f);
            float4 nb = na;
            const int pc = ch + 3;
            if (pc < SPAN_CHUNKS) {
                const float* pn = xs + pc * CHUNK + lbase;
                na = __ldcs(reinterpret_cast<const float4*>(pn));
                nb = __ldcs(reinterpret_cast<const float4*>(pn + 4));
            } else if (next_valid) {
                const float* pn = nxs + (pc - SPAN_CHUNKS) * CHUNK + lbase;
                na = __ldcs(reinterpret_cast<const float4*>(pn));
                nb = __ldcs(reinterpret_cast<const float4*>(pn + 4));
            }

            float v[LPT] = {a0.x, a0.y, a0.z, a0.w, b0.x, b0.y, b0.z, b0.w};

            // Neighbor: rotate shfl gives lane i the last element of lane i-1;
            // lane 0 substitutes the previous chunk's lane-31 element, or at
            // the span start: boundary x (q>0) / v[0] (q==0 -> diff 0).
            const float rot = __shfl_sync(0xffffffffu, v[LPT - 1], rsrc);
            float prev = rot;
            if (lane == 0u)
                prev = (ch == 0) ? ((q > 0u) ? boundary : v[0]) : saved;
            saved = rot;

            // Lane-local inclusive scan of tanh(diffs).
            float s[LPT];
            float run = 0.0f, p = prev;
#pragma unroll
            for (int i = 0; i < LPT; i++) {
                run += fast_tanh(v[i] - p);
                p = v[i];
                s[i] = run;
            }
            const float tot = run;

            // Warp inclusive scan of lane totals.
            float ws = tot;
#pragma unroll
            for (int off = 1; off < 32; off <<= 1) {
                float n = __shfl_up_sync(0xffffffffu, ws, off);
                if (lane >= (unsigned)off) ws += n;
            }

            const float prefix = carry + (ws - tot);   // exclusive

            float* po = os + ch * CHUNK + lbase;
            __stcs(reinterpret_cast<float4*>(po),
                   make_float4(prefix + s[0], prefix + s[1],
                               prefix + s[2], prefix + s[3]));
            __stcs(reinterpret_cast<float4*>(po + 4),
                   make_float4(prefix + s[4], prefix + s[5],
                               prefix + s[6], prefix + s[7]));

            carry += __shfl_sync(0xffffffffu, ws, 31);

            // Rotate depth-3 pipeline.
            a0 = a1; b0 = b1;
            a1 = a2; b1 = b2;
            a2 = na; b2 = nb;
        }

        // Publish inclusive prefix for the successor quarter (q<3).
        if (q < (unsigned)(QPER - 1) && lane == 0u) {
            unsigned long long w =
                ((unsigned long long)epoch << 32) |
                (unsigned long long)__float_as_uint(carry);
            *(volatile unsigned long long*)&g_hand[(row << 2) + q] = w;
        }

        if (!next_valid) break;
        task = next_task;
        q    = nq;
        row  = nrow;
        xs   = nxs;
        os   = out + (size_t)row * S + (size_t)q * SPAN;
        next_task = fetch_task(lane);
    }
}

extern "C" void kernel_launch(void* const* d_in, const int* in_sizes, int n_in,
                              void* d_out, int out_size)
{
    const float* x = (const float*)d_in[0];
    float* out     = (float*)d_out;
    (void)in_sizes; (void)n_in; (void)out_size;

    epoch_kernel<<<1, 1>>>();
    softindex_kernel<<<GRID, THREADS>>>(x, out);
}